// round 1
// baseline (speedup 1.0000x reference)
#include <cuda_runtime.h>
#include <math.h>

#define E_ 8
#define D_ 1024
#define H_ 2048
#define T_ 2048

// Scratch (device globals: allocation-free per harness rules)
__device__ float g_h[(size_t)E_ * T_ * H_];   // per-expert hidden activations
__device__ int   g_cnt[E_];                   // tokens routed to each expert
__device__ int   g_tok[E_ * T_];              // token id per expert slot
__device__ float g_wt[E_ * T_];               // gate weight per expert slot

// ---------------------------------------------------------------------------
// Kernel 0: zero output accumulator + routing counters
// grid 2048 x 256 threads x float4 == T_*D_ floats
// ---------------------------------------------------------------------------
__global__ void zero_kernel(float* __restrict__ out) {
    size_t i = (size_t)blockIdx.x * blockDim.x + threadIdx.x;
    ((float4*)out)[i] = make_float4(0.f, 0.f, 0.f, 0.f);
    if (blockIdx.x == 0 && threadIdx.x < E_) g_cnt[threadIdx.x] = 0;
}

// ---------------------------------------------------------------------------
// Kernel 1: gate — logits = x@Wg + bg, top-2, softmax, routing, top_idx out
// one block (256 thr) per token
// ---------------------------------------------------------------------------
__global__ __launch_bounds__(256) void gate_kernel(
    const float* __restrict__ x, const float* __restrict__ Wg,
    const float* __restrict__ bg, float* __restrict__ out)
{
    int t = blockIdx.x;
    const float* xr = x + (size_t)t * D_;

    float acc[E_];
#pragma unroll
    for (int e = 0; e < E_; e++) acc[e] = 0.f;

    for (int d = threadIdx.x; d < D_; d += 256) {
        float xv = xr[d];
        const float4* wr = (const float4*)(Wg + (size_t)d * E_);
        float4 w0 = wr[0], w1 = wr[1];
        acc[0] += xv * w0.x; acc[1] += xv * w0.y;
        acc[2] += xv * w0.z; acc[3] += xv * w0.w;
        acc[4] += xv * w1.x; acc[5] += xv * w1.y;
        acc[6] += xv * w1.z; acc[7] += xv * w1.w;
    }

    // warp reduce
#pragma unroll
    for (int off = 16; off > 0; off >>= 1)
#pragma unroll
        for (int e = 0; e < E_; e++)
            acc[e] += __shfl_down_sync(0xffffffffu, acc[e], off);

    __shared__ float sm[8][E_];
    int warp = threadIdx.x >> 5, lane = threadIdx.x & 31;
    if (lane == 0)
#pragma unroll
        for (int e = 0; e < E_; e++) sm[warp][e] = acc[e];
    __syncthreads();

    if (threadIdx.x == 0) {
        float lg[E_];
#pragma unroll
        for (int e = 0; e < E_; e++) {
            float s = bg[e];
#pragma unroll
            for (int w = 0; w < 8; w++) s += sm[w][e];
            lg[e] = s;
        }
        // top-2 (ties: lowest index first, matching lax.top_k)
        int e0 = 0;
#pragma unroll
        for (int e = 1; e < E_; e++) if (lg[e] > lg[e0]) e0 = e;
        int e1 = -1;
#pragma unroll
        for (int e = 0; e < E_; e++)
            if (e != e0 && (e1 < 0 || lg[e] > lg[e1])) e1 = e;

        // softmax over [lg[e0], lg[e1]] with max subtraction
        float ex = expf(lg[e1] - lg[e0]);
        float inv = 1.f / (1.f + ex);
        float w0 = inv, w1 = ex * inv;

        // top_idx appended after moe_outp, as floats
        out[(size_t)T_ * D_ + 2 * t]     = (float)e0;
        out[(size_t)T_ * D_ + 2 * t + 1] = (float)e1;

        int p0 = atomicAdd(&g_cnt[e0], 1);
        g_tok[e0 * T_ + p0] = t;  g_wt[e0 * T_ + p0] = w0;
        int p1 = atomicAdd(&g_cnt[e1], 1);
        g_tok[e1 * T_ + p1] = t;  g_wt[e1 * T_ + p1] = w1;
    }
}

// ---------------------------------------------------------------------------
// Tiled fp32 GEMMs: 128x128 tile, BK=8, 256 threads, 8x8 microtile
// ---------------------------------------------------------------------------
#define BM 128
#define BN 128
#define BK 8

__device__ __forceinline__ float gelu_tanh(float v) {
    // jax.nn.gelu approximate=True
    float v3 = v * v * v;
    return 0.5f * v * (1.f + tanhf(0.7978845608028654f * (v + 0.044715f * v3)));
}

// GEMM1: h[e] = gelu( gather(X, tok[e]) @ W1[e] + b1[e] )   [ne x H_]
__global__ __launch_bounds__(256) void gemm1_kernel(
    const float* __restrict__ X, const float* __restrict__ W1,
    const float* __restrict__ b1)
{
    int e = blockIdx.z;
    int ne = g_cnt[e];
    int row0 = blockIdx.x * BM;
    if (row0 >= ne) return;
    int n0 = blockIdx.y * BN;
    const float* W = W1 + (size_t)e * D_ * H_;

    __shared__ float As[BK][BM];
    __shared__ float Bs[BK][BN];

    int tid = threadIdx.x;
    int ar = tid >> 1;            // A row within tile (0..127)
    int ak = (tid & 1) * 4;       // A k sub-offset (0 or 4)
    int atok = -1;
    {
        int r = row0 + ar;
        if (r < ne) atok = g_tok[e * T_ + r];
    }
    int bk = tid >> 5;            // B k row (0..7)
    int bn = (tid & 31) * 4;      // B col offset
    int tx = tid & 15, ty = tid >> 4;

    float acc[8][8];
#pragma unroll
    for (int i = 0; i < 8; i++)
#pragma unroll
        for (int j = 0; j < 8; j++) acc[i][j] = 0.f;

    for (int k0 = 0; k0 < D_; k0 += BK) {
        float4 av = make_float4(0.f, 0.f, 0.f, 0.f);
        if (atok >= 0)
            av = *(const float4*)(X + (size_t)atok * D_ + k0 + ak);
        float4 bv = *(const float4*)(W + (size_t)(k0 + bk) * H_ + n0 + bn);

        __syncthreads();
        As[ak + 0][ar] = av.x; As[ak + 1][ar] = av.y;
        As[ak + 2][ar] = av.z; As[ak + 3][ar] = av.w;
        *(float4*)&Bs[bk][bn] = bv;
        __syncthreads();

#pragma unroll
        for (int kk = 0; kk < BK; kk++) {
            float4 a0 = *(float4*)&As[kk][ty * 8];
            float4 a1 = *(float4*)&As[kk][ty * 8 + 4];
            float4 b0 = *(float4*)&Bs[kk][tx * 8];
            float4 b1v = *(float4*)&Bs[kk][tx * 8 + 4];
            float a[8] = {a0.x, a0.y, a0.z, a0.w, a1.x, a1.y, a1.z, a1.w};
            float b[8] = {b0.x, b0.y, b0.z, b0.w, b1v.x, b1v.y, b1v.z, b1v.w};
#pragma unroll
            for (int i = 0; i < 8; i++)
#pragma unroll
                for (int j = 0; j < 8; j++) acc[i][j] += a[i] * b[j];
        }
    }

    const float* bb = b1 + (size_t)e * H_ + n0;
#pragma unroll
    for (int i = 0; i < 8; i++) {
        int r = row0 + ty * 8 + i;
        if (r >= ne) continue;
        float* hrow = g_h + ((size_t)e * T_ + r) * H_ + n0 + tx * 8;
        float4 o0, o1;
        o0.x = gelu_tanh(acc[i][0] + bb[tx * 8 + 0]);
        o0.y = gelu_tanh(acc[i][1] + bb[tx * 8 + 1]);
        o0.z = gelu_tanh(acc[i][2] + bb[tx * 8 + 2]);
        o0.w = gelu_tanh(acc[i][3] + bb[tx * 8 + 3]);
        o1.x = gelu_tanh(acc[i][4] + bb[tx * 8 + 4]);
        o1.y = gelu_tanh(acc[i][5] + bb[tx * 8 + 5]);
        o1.z = gelu_tanh(acc[i][6] + bb[tx * 8 + 6]);
        o1.w = gelu_tanh(acc[i][7] + bb[tx * 8 + 7]);
        *(float4*)(hrow)     = o0;
        *(float4*)(hrow + 4) = o1;
    }
}

// GEMM2: out[tok] += w * ( h[e] @ W2[e] + b2[e] )
__global__ __launch_bounds__(256) void gemm2_kernel(
    const float* __restrict__ W2, const float* __restrict__ b2,
    float* __restrict__ out)
{
    int e = blockIdx.z;
    int ne = g_cnt[e];
    int row0 = blockIdx.x * BM;
    if (row0 >= ne) return;
    int n0 = blockIdx.y * BN;
    const float* A = g_h + (size_t)e * T_ * H_;
    const float* W = W2 + (size_t)e * H_ * D_;

    __shared__ float As[BK][BM];
    __shared__ float Bs[BK][BN];

    int tid = threadIdx.x;
    int ar = tid >> 1;
    int ak = (tid & 1) * 4;
    bool avalid = (row0 + ar) < ne;
    const float* arow = A + (size_t)(row0 + ar) * H_;
    int bk = tid >> 5;
    int bn = (tid & 31) * 4;
    int tx = tid & 15, ty = tid >> 4;

    float acc[8][8];
#pragma unroll
    for (int i = 0; i < 8; i++)
#pragma unroll
        for (int j = 0; j < 8; j++) acc[i][j] = 0.f;

    for (int k0 = 0; k0 < H_; k0 += BK) {
        float4 av = make_float4(0.f, 0.f, 0.f, 0.f);
        if (avalid)
            av = *(const float4*)(arow + k0 + ak);
        float4 bv = *(const float4*)(W + (size_t)(k0 + bk) * D_ + n0 + bn);

        __syncthreads();
        As[ak + 0][ar] = av.x; As[ak + 1][ar] = av.y;
        As[ak + 2][ar] = av.z; As[ak + 3][ar] = av.w;
        *(float4*)&Bs[bk][bn] = bv;
        __syncthreads();

#pragma unroll
        for (int kk = 0; kk < BK; kk++) {
            float4 a0 = *(float4*)&As[kk][ty * 8];
            float4 a1 = *(float4*)&As[kk][ty * 8 + 4];
            float4 b0 = *(float4*)&Bs[kk][tx * 8];
            float4 b1v = *(float4*)&Bs[kk][tx * 8 + 4];
            float a[8] = {a0.x, a0.y, a0.z, a0.w, a1.x, a1.y, a1.z, a1.w};
            float b[8] = {b0.x, b0.y, b0.z, b0.w, b1v.x, b1v.y, b1v.z, b1v.w};
#pragma unroll
            for (int i = 0; i < 8; i++)
#pragma unroll
                for (int j = 0; j < 8; j++) acc[i][j] += a[i] * b[j];
        }
    }

    const float* bb = b2 + (size_t)e * D_ + n0;
#pragma unroll
    for (int i = 0; i < 8; i++) {
        int r = row0 + ty * 8 + i;
        if (r >= ne) continue;
        int t = g_tok[e * T_ + r];
        float w = g_wt[e * T_ + r];
        float* orow = out + (size_t)t * D_ + n0 + tx * 8;
#pragma unroll
        for (int j = 0; j < 8; j++)
            atomicAdd(&orow[j], w * (acc[i][j] + bb[tx * 8 + j]));
    }
}

// ---------------------------------------------------------------------------
extern "C" void kernel_launch(void* const* d_in, const int* in_sizes, int n_in,
                              void* d_out, int out_size)
{
    const float* x  = (const float*)d_in[0];
    const float* Wg = (const float*)d_in[1];
    const float* bg = (const float*)d_in[2];
    const float* W1 = (const float*)d_in[3];
    const float* b1 = (const float*)d_in[4];
    const float* W2 = (const float*)d_in[5];
    const float* b2 = (const float*)d_in[6];
    float* out = (float*)d_out;

    zero_kernel<<<(T_ * D_) / (256 * 4), 256>>>(out);
    gate_kernel<<<T_, 256>>>(x, Wg, bg, out);
    gemm1_kernel<<<dim3(T_ / BM, H_ / BN, E_), 256>>>(x, W1, b1);
    gemm2_kernel<<<dim3(T_ / BM, D_ / BN, E_), 256>>>(W2, b2, out);
}

// round 5
// speedup vs baseline: 2.0796x; 2.0796x over previous
#include <cuda_runtime.h>
#include <cuda_bf16.h>
#include <math.h>
#include <stdint.h>

#define E_ 8
#define D_ 1024
#define H_ 2048
#define T_ 2048

#define BM 128
#define BN 128
#define BK 16
#define LDP 136   // smem row stride in floats (128 + 8 pad -> conflict-free frags)

// ---------------------------------------------------------------------------
// Device scratch (allocation-free per harness rules)
// ---------------------------------------------------------------------------
__device__ float g_h[(size_t)E_ * T_ * H_];   // per-expert hidden activations (by slot)
__device__ int   g_cnt[E_];
__device__ int   g_tok[E_ * T_];
__device__ float g_wt[E_ * T_];

// ---------------------------------------------------------------------------
__device__ __forceinline__ uint32_t f2tf32(float v) {
    uint32_t r;
    asm("cvt.rna.tf32.f32 %0, %1;" : "=r"(r) : "f"(v));
    return r;
}

__device__ __forceinline__ void mma_tf32(float* c, const uint32_t* a, const uint32_t* b) {
    asm volatile(
        "mma.sync.aligned.m16n8k8.row.col.f32.tf32.tf32.f32 "
        "{%0,%1,%2,%3}, {%4,%5,%6,%7}, {%8,%9}, {%0,%1,%2,%3};"
        : "+f"(c[0]), "+f"(c[1]), "+f"(c[2]), "+f"(c[3])
        : "r"(a[0]), "r"(a[1]), "r"(a[2]), "r"(a[3]), "r"(b[0]), "r"(b[1]));
}

__device__ __forceinline__ float gelu_tanh(float v) {
    float v3 = v * v * v;
    return 0.5f * v * (1.f + tanhf(0.7978845608028654f * (v + 0.044715f * v3)));
}

// ---------------------------------------------------------------------------
// Kernel: zero output + counters
// ---------------------------------------------------------------------------
__global__ void zero_kernel(float* __restrict__ out) {
    size_t i = (size_t)blockIdx.x * blockDim.x + threadIdx.x;
    ((float4*)out)[i] = make_float4(0.f, 0.f, 0.f, 0.f);
    if (blockIdx.x == 0 && threadIdx.x < E_) g_cnt[threadIdx.x] = 0;
}

// ---------------------------------------------------------------------------
// Kernel: gate (verified in R1)
// ---------------------------------------------------------------------------
__global__ __launch_bounds__(256) void gate_kernel(
    const float* __restrict__ x, const float* __restrict__ Wg,
    const float* __restrict__ bg, float* __restrict__ out)
{
    int t = blockIdx.x;
    const float* xr = x + (size_t)t * D_;

    float acc[E_];
#pragma unroll
    for (int e = 0; e < E_; e++) acc[e] = 0.f;

    for (int d = threadIdx.x; d < D_; d += 256) {
        float xv = xr[d];
        const float4* wr = (const float4*)(Wg + (size_t)d * E_);
        float4 w0 = wr[0], w1 = wr[1];
        acc[0] += xv * w0.x; acc[1] += xv * w0.y;
        acc[2] += xv * w0.z; acc[3] += xv * w0.w;
        acc[4] += xv * w1.x; acc[5] += xv * w1.y;
        acc[6] += xv * w1.z; acc[7] += xv * w1.w;
    }
#pragma unroll
    for (int off = 16; off > 0; off >>= 1)
#pragma unroll
        for (int e = 0; e < E_; e++)
            acc[e] += __shfl_down_sync(0xffffffffu, acc[e], off);

    __shared__ float sm[8][E_];
    int warp = threadIdx.x >> 5, lane = threadIdx.x & 31;
    if (lane == 0)
#pragma unroll
        for (int e = 0; e < E_; e++) sm[warp][e] = acc[e];
    __syncthreads();

    if (threadIdx.x == 0) {
        float lg[E_];
#pragma unroll
        for (int e = 0; e < E_; e++) {
            float s = bg[e];
#pragma unroll
            for (int w = 0; w < 8; w++) s += sm[w][e];
            lg[e] = s;
        }
        int e0 = 0;
#pragma unroll
        for (int e = 1; e < E_; e++) if (lg[e] > lg[e0]) e0 = e;
        int e1 = -1;
#pragma unroll
        for (int e = 0; e < E_; e++)
            if (e != e0 && (e1 < 0 || lg[e] > lg[e1])) e1 = e;

        float ex = expf(lg[e1] - lg[e0]);
        float inv = 1.f / (1.f + ex);
        float w0 = inv, w1 = ex * inv;

        out[(size_t)T_ * D_ + 2 * t]     = (float)e0;
        out[(size_t)T_ * D_ + 2 * t + 1] = (float)e1;

        int p0 = atomicAdd(&g_cnt[e0], 1);
        g_tok[e0 * T_ + p0] = t;  g_wt[e0 * T_ + p0] = w0;
        int p1 = atomicAdd(&g_cnt[e1], 1);
        g_tok[e1 * T_ + p1] = t;  g_wt[e1 * T_ + p1] = w1;
    }
}

// ===========================================================================
// tf32 mma.sync GEMM mainloop (shared by both FFN layers)
//   - 128x128 block tile, BK=16, 256 threads, 8 warps at 64x32 warp tiles
//   - A staged [k][m] (transposed), B staged [k][n]; both tf32-converted
//   - acc[mi][ni][q]: warp (wm,wn) covers rows wm*64+mi*16+{g8, g8+8},
//     cols wn*32+ni*8+{2*t4, 2*t4+1}
//   - Staging: A: thread -> m=tid&127, ksub=(tid>>7)*8 (8 scalar STS)
//              B: thread -> k=tid>>4, nsub=(tid&15)*8  (2 vec4 STS)
// ===========================================================================
template <int NCH>
__device__ __forceinline__ void gemm_mainloop(
    float (*As)[BK][LDP], float (*Bs)[BK][LDP],
    const float* arow, const float* bptr, int bstride,
    int sma, int ska, int skb, int snb,
    float acc[4][4][4])
{
    const int tid = threadIdx.x;
    const int lane = tid & 31, wid = tid >> 5;
    const int wm = wid & 1, wn = wid >> 1;
    const int t4 = lane & 3, g8 = lane >> 2;

#pragma unroll
    for (int i = 0; i < 4; i++)
#pragma unroll
        for (int j = 0; j < 4; j++)
#pragma unroll
            for (int q = 0; q < 4; q++) acc[i][j][q] = 0.f;

    // prologue: stage chunk 0 into buf 0
    {
        float4 a0 = *(const float4*)(arow);
        float4 a1 = *(const float4*)(arow + 4);
        float4 b0 = *(const float4*)(bptr);
        float4 b1 = *(const float4*)(bptr + 4);
        float av[8] = {a0.x, a0.y, a0.z, a0.w, a1.x, a1.y, a1.z, a1.w};
#pragma unroll
        for (int j = 0; j < 8; j++)
            As[0][ska + j][sma] = __uint_as_float(f2tf32(av[j]));
        uint4 bh;
        bh.x = f2tf32(b0.x); bh.y = f2tf32(b0.y); bh.z = f2tf32(b0.z); bh.w = f2tf32(b0.w);
        *(uint4*)&Bs[0][skb][snb] = bh;
        bh.x = f2tf32(b1.x); bh.y = f2tf32(b1.y); bh.z = f2tf32(b1.z); bh.w = f2tf32(b1.w);
        *(uint4*)&Bs[0][skb][snb + 4] = bh;
    }

    for (int ch = 0; ch < NCH; ++ch) {
        __syncthreads();
        int b = ch & 1;
        float4 pa0, pa1, pb0, pb1;
        bool pf = (ch + 1) < NCH;
        if (pf) {
            const float* ap = arow + (ch + 1) * BK;
            const float* bp = bptr + (size_t)(ch + 1) * BK * bstride;
            pa0 = *(const float4*)(ap);
            pa1 = *(const float4*)(ap + 4);
            pb0 = *(const float4*)(bp);
            pb1 = *(const float4*)(bp + 4);
        }
#pragma unroll
        for (int kh = 0; kh < 2; ++kh) {
            int k0 = kh * 8;
            uint32_t af[4][4], bf[4][2];
#pragma unroll
            for (int mi = 0; mi < 4; mi++) {
                int rm = wm * 64 + mi * 16;
                af[mi][0] = __float_as_uint(As[b][k0 + t4][rm + g8]);
                af[mi][1] = __float_as_uint(As[b][k0 + t4][rm + g8 + 8]);
                af[mi][2] = __float_as_uint(As[b][k0 + t4 + 4][rm + g8]);
                af[mi][3] = __float_as_uint(As[b][k0 + t4 + 4][rm + g8 + 8]);
            }
#pragma unroll
            for (int ni = 0; ni < 4; ni++) {
                int cb = wn * 32 + ni * 8 + g8;
                bf[ni][0] = __float_as_uint(Bs[b][k0 + t4][cb]);
                bf[ni][1] = __float_as_uint(Bs[b][k0 + t4 + 4][cb]);
            }
#pragma unroll
            for (int mi = 0; mi < 4; mi++)
#pragma unroll
                for (int ni = 0; ni < 4; ni++)
                    mma_tf32(acc[mi][ni], af[mi], bf[ni]);
        }
        if (pf) {
            int nb = b ^ 1;
            float av[8] = {pa0.x, pa0.y, pa0.z, pa0.w, pa1.x, pa1.y, pa1.z, pa1.w};
#pragma unroll
            for (int j = 0; j < 8; j++)
                As[nb][ska + j][sma] = __uint_as_float(f2tf32(av[j]));
            uint4 bh;
            bh.x = f2tf32(pb0.x); bh.y = f2tf32(pb0.y); bh.z = f2tf32(pb0.z); bh.w = f2tf32(pb0.w);
            *(uint4*)&Bs[nb][skb][snb] = bh;
            bh.x = f2tf32(pb1.x); bh.y = f2tf32(pb1.y); bh.z = f2tf32(pb1.z); bh.w = f2tf32(pb1.w);
            *(uint4*)&Bs[nb][skb][snb + 4] = bh;
        }
    }
}

// ---------------------------------------------------------------------------
// GEMM1: h[slot] = gelu(X[tok] @ W1[e] + b1[e])
// ---------------------------------------------------------------------------
__global__ __launch_bounds__(256) void gemm1_mma(
    const float* __restrict__ X, const float* __restrict__ W1,
    const float* __restrict__ b1)
{
    int e = blockIdx.z;
    int ne = g_cnt[e];
    int row0 = blockIdx.x * BM;
    if (row0 >= ne) return;
    int n0 = blockIdx.y * BN;

    __shared__ float As[2][BK][LDP];
    __shared__ float Bs[2][BK][LDP];
    __shared__ int s_tok[BM];

    int tid = threadIdx.x;
    if (tid < BM) {
        int r = row0 + tid;
        s_tok[tid] = (r < ne) ? g_tok[e * T_ + r] : 0;
    }
    __syncthreads();

    const int sma = tid & 127;
    const int ska = (tid >> 7) * 8;
    const int skb = tid >> 4;
    const int snb = (tid & 15) * 8;

    const float* arow = X + (size_t)s_tok[sma] * D_ + ska;
    const float* bptr = W1 + (size_t)e * D_ * H_ + (size_t)skb * H_ + n0 + snb;

    float acc[4][4][4];
    gemm_mainloop<D_ / BK>(As, Bs, arow, bptr, H_, sma, ska, skb, snb, acc);

    // Epilogue: bias + gelu -> g_h (fp32, by slot)
    const int lane = tid & 31, wid = tid >> 5;
    const int wm = wid & 1, wn = wid >> 1;
    const int t4 = lane & 3, g8 = lane >> 2;
    const float* bb = b1 + (size_t)e * H_ + n0;
#pragma unroll
    for (int mi = 0; mi < 4; mi++) {
        int rl0 = wm * 64 + mi * 16 + g8;
#pragma unroll
        for (int half = 0; half < 2; half++) {
            int rl = rl0 + half * 8;
            int r = row0 + rl;
            if (r >= ne) continue;
            float* orow = g_h + ((size_t)(e * T_ + r)) * H_ + n0;
#pragma unroll
            for (int ni = 0; ni < 4; ni++) {
                int cn = wn * 32 + ni * 8 + t4 * 2;
                float v0 = acc[mi][ni][half * 2]     + bb[cn];
                float v1 = acc[mi][ni][half * 2 + 1] + bb[cn + 1];
                float2 o = make_float2(gelu_tanh(v0), gelu_tanh(v1));
                *(float2*)(orow + cn) = o;
            }
        }
    }
}

// ---------------------------------------------------------------------------
// GEMM2: out[tok] += w * (h[slot] @ W2[e] + b2[e])
// ---------------------------------------------------------------------------
__global__ __launch_bounds__(256) void gemm2_mma(
    const float* __restrict__ W2, const float* __restrict__ b2,
    float* __restrict__ out)
{
    int e = blockIdx.z;
    int ne = g_cnt[e];
    int row0 = blockIdx.x * BM;
    if (row0 >= ne) return;
    int n0 = blockIdx.y * BN;

    __shared__ float As[2][BK][LDP];
    __shared__ float Bs[2][BK][LDP];

    int tid = threadIdx.x;

    const int sma = tid & 127;
    const int ska = (tid >> 7) * 8;
    const int skb = tid >> 4;
    const int snb = (tid & 15) * 8;

    // A rows beyond ne read stale scratch: harmless (results masked in epilogue)
    const float* arow = g_h + ((size_t)(e * T_ + row0 + sma)) * H_ + ska;
    const float* bptr = W2 + (size_t)e * H_ * D_ + (size_t)skb * D_ + n0 + snb;

    float acc[4][4][4];
    gemm_mainloop<H_ / BK>(As, Bs, arow, bptr, D_, sma, ska, skb, snb, acc);

    // Epilogue: bias + gate-weight scale + atomic combine
    const int lane = tid & 31, wid = tid >> 5;
    const int wm = wid & 1, wn = wid >> 1;
    const int t4 = lane & 3, g8 = lane >> 2;
    const float* bb = b2 + (size_t)e * D_ + n0;
#pragma unroll
    for (int mi = 0; mi < 4; mi++) {
        int rl0 = wm * 64 + mi * 16 + g8;
#pragma unroll
        for (int half = 0; half < 2; half++) {
            int rl = rl0 + half * 8;
            int r = row0 + rl;
            if (r >= ne) continue;
            int tok = g_tok[e * T_ + r];
            float wgt = g_wt[e * T_ + r];
            float* orow = out + (size_t)tok * D_ + n0;
#pragma unroll
            for (int ni = 0; ni < 4; ni++) {
                int cn = wn * 32 + ni * 8 + t4 * 2;
                atomicAdd(orow + cn,     wgt * (acc[mi][ni][half * 2]     + bb[cn]));
                atomicAdd(orow + cn + 1, wgt * (acc[mi][ni][half * 2 + 1] + bb[cn + 1]));
            }
        }
    }
}

// ---------------------------------------------------------------------------
extern "C" void kernel_launch(void* const* d_in, const int* in_sizes, int n_in,
                              void* d_out, int out_size)
{
    const float* x  = (const float*)d_in[0];
    const float* Wg = (const float*)d_in[1];
    const float* bg = (const float*)d_in[2];
    const float* W1 = (const float*)d_in[3];
    const float* b1 = (const float*)d_in[4];
    const float* W2 = (const float*)d_in[5];
    const float* b2 = (const float*)d_in[6];
    float* out = (float*)d_out;

    zero_kernel<<<(T_ * D_) / (256 * 4), 256>>>(out);
    gate_kernel<<<T_, 256>>>(x, Wg, bg, out);
    gemm1_mma<<<dim3(T_ / BM, H_ / BN, E_), 256>>>(x, W1, b1);
    gemm2_mma<<<dim3(T_ / BM, D_ / BN, E_), 256>>>(W2, b2, out);
}

// round 6
// speedup vs baseline: 3.0527x; 1.4679x over previous
#include <cuda_runtime.h>
#include <cuda_bf16.h>
#include <math.h>
#include <stdint.h>

#define E_ 8
#define D_ 1024
#define H_ 2048
#define T_ 2048

#define BM 128
#define BN 128
#define BK 16

// SMEM stage geometry (floats)
#define A_STRIDE 20            // 16 + 4 pad -> conflict-free A frag loads
#define B_STRIDE 136           // 128 + 8 pad -> conflict-free B frag loads
#define A_FLOATS (BM * A_STRIDE)            // 2560
#define B_FLOATS (BK * B_STRIDE)            // 2176
#define STG_FLOATS (A_FLOATS + B_FLOATS)    // 4736
#define STG_BYTES (STG_FLOATS * 4)          // 18944
#define NSTAGE 4
#define SMEM_BYTES (NSTAGE * STG_BYTES)     // 75776

// ---------------------------------------------------------------------------
// Device scratch (allocation-free per harness rules)
// ---------------------------------------------------------------------------
__device__ float g_h[(size_t)E_ * T_ * H_];     // hidden acts (tf32-rounded fp32)
__device__ float g_Xr[(size_t)T_ * D_];         // X  tf32-rounded
__device__ float g_W1r[(size_t)E_ * D_ * H_];   // W1 tf32-rounded
__device__ float g_W2r[(size_t)E_ * H_ * D_];   // W2 tf32-rounded
__device__ int   g_cnt[E_];
__device__ int   g_tok[E_ * T_];
__device__ float g_wt[E_ * T_];

// ---------------------------------------------------------------------------
__device__ __forceinline__ uint32_t f2tf32(float v) {
    uint32_t r;
    asm("cvt.rna.tf32.f32 %0, %1;" : "=r"(r) : "f"(v));
    return r;
}

__device__ __forceinline__ void mma_tf32(float* c, const uint32_t* a, const uint32_t* b) {
    asm volatile(
        "mma.sync.aligned.m16n8k8.row.col.f32.tf32.tf32.f32 "
        "{%0,%1,%2,%3}, {%4,%5,%6,%7}, {%8,%9}, {%0,%1,%2,%3};"
        : "+f"(c[0]), "+f"(c[1]), "+f"(c[2]), "+f"(c[3])
        : "r"(a[0]), "r"(a[1]), "r"(a[2]), "r"(a[3]), "r"(b[0]), "r"(b[1]));
}

__device__ __forceinline__ uint32_t smem_u32(const void* p) {
    uint32_t a;
    asm("{ .reg .u64 t; cvta.to.shared.u64 t, %1; cvt.u32.u64 %0, t; }"
        : "=r"(a) : "l"(p));
    return a;
}

#define CP16(dst, src) \
    asm volatile("cp.async.cg.shared.global [%0], [%1], 16;" :: "r"(dst), "l"(src))
#define CP_COMMIT() asm volatile("cp.async.commit_group;")
#define CP_WAIT2()  asm volatile("cp.async.wait_group 2;")

__device__ __forceinline__ float gelu_tanh(float v) {
    float v3 = v * v * v;
    return 0.5f * v * (1.f + tanhf(0.7978845608028654f * (v + 0.044715f * v3)));
}

// ---------------------------------------------------------------------------
// Kernel: zero output + counters
// ---------------------------------------------------------------------------
__global__ void zero_kernel(float* __restrict__ out) {
    size_t i = (size_t)blockIdx.x * blockDim.x + threadIdx.x;
    ((float4*)out)[i] = make_float4(0.f, 0.f, 0.f, 0.f);
    if (blockIdx.x == 0 && threadIdx.x < E_) g_cnt[threadIdx.x] = 0;
}

// ---------------------------------------------------------------------------
// Kernel: tf32 round pre-pass (grid-stride over float4)
// ---------------------------------------------------------------------------
__global__ void rnd_kernel(const float* __restrict__ s, float* __restrict__ d) {
    size_t i = ((size_t)blockIdx.x * 256 + threadIdx.x) * 4;
    float4 v = *(const float4*)(s + i);
    uint4 o;
    o.x = f2tf32(v.x); o.y = f2tf32(v.y); o.z = f2tf32(v.z); o.w = f2tf32(v.w);
    *(uint4*)(d + i) = o;
}

// ---------------------------------------------------------------------------
// Kernel: gate (verified)
// ---------------------------------------------------------------------------
__global__ __launch_bounds__(256) void gate_kernel(
    const float* __restrict__ x, const float* __restrict__ Wg,
    const float* __restrict__ bg, float* __restrict__ out)
{
    int t = blockIdx.x;
    const float* xr = x + (size_t)t * D_;

    float acc[E_];
#pragma unroll
    for (int e = 0; e < E_; e++) acc[e] = 0.f;

    for (int d = threadIdx.x; d < D_; d += 256) {
        float xv = xr[d];
        const float4* wr = (const float4*)(Wg + (size_t)d * E_);
        float4 w0 = wr[0], w1 = wr[1];
        acc[0] += xv * w0.x; acc[1] += xv * w0.y;
        acc[2] += xv * w0.z; acc[3] += xv * w0.w;
        acc[4] += xv * w1.x; acc[5] += xv * w1.y;
        acc[6] += xv * w1.z; acc[7] += xv * w1.w;
    }
#pragma unroll
    for (int off = 16; off > 0; off >>= 1)
#pragma unroll
        for (int e = 0; e < E_; e++)
            acc[e] += __shfl_down_sync(0xffffffffu, acc[e], off);

    __shared__ float sm[8][E_];
    int warp = threadIdx.x >> 5, lane = threadIdx.x & 31;
    if (lane == 0)
#pragma unroll
        for (int e = 0; e < E_; e++) sm[warp][e] = acc[e];
    __syncthreads();

    if (threadIdx.x == 0) {
        float lg[E_];
#pragma unroll
        for (int e = 0; e < E_; e++) {
            float s = bg[e];
#pragma unroll
            for (int w = 0; w < 8; w++) s += sm[w][e];
            lg[e] = s;
        }
        int e0 = 0;
#pragma unroll
        for (int e = 1; e < E_; e++) if (lg[e] > lg[e0]) e0 = e;
        int e1 = -1;
#pragma unroll
        for (int e = 0; e < E_; e++)
            if (e != e0 && (e1 < 0 || lg[e] > lg[e1])) e1 = e;

        float ex = expf(lg[e1] - lg[e0]);
        float inv = 1.f / (1.f + ex);
        float w0 = inv, w1 = ex * inv;

        out[(size_t)T_ * D_ + 2 * t]     = (float)e0;
        out[(size_t)T_ * D_ + 2 * t + 1] = (float)e1;

        int p0 = atomicAdd(&g_cnt[e0], 1);
        g_tok[e0 * T_ + p0] = t;  g_wt[e0 * T_ + p0] = w0;
        int p1 = atomicAdd(&g_cnt[e1], 1);
        g_tok[e1 * T_ + p1] = t;  g_wt[e1 * T_ + p1] = w1;
    }
}

// ===========================================================================
// 4-stage cp.async tf32 GEMM mainloop
//   A smem [m][k] stride 20, B smem [k][n] stride 136, operands pre-rounded.
//   Per thread staging: A segs {tid, tid+256}: row=seg>>2 (rows r, r+64),
//   ksub=(tid&3)*4.  B segs {tid, tid+256}: k=seg>>5 (k, k+8), nsub=(tid&31)*4.
// ===========================================================================
template <int NCH>
__device__ __forceinline__ void gemm_pipe(
    float* sm, uint32_t smb,
    const float* aptr0, const float* aptr1,     // per-thread A sources (chunk 0)
    const float* bptr0, const float* bptr1,     // per-thread B sources (chunk 0)
    int bstride, float acc[4][4][4])
{
    const int tid = threadIdx.x;
    const int lane = tid & 31, wid = tid >> 5;
    const int wm = wid & 1, wn = wid >> 1;
    const int t4 = lane & 3, g8 = lane >> 2;

    const int a_row = tid >> 2, ks = (tid & 3) * 4;
    const int b_k = tid >> 5, ns = (tid & 31) * 4;
    const uint32_t dA0 = (uint32_t)((a_row * A_STRIDE + ks) * 4);
    const uint32_t dA1 = (uint32_t)(((a_row + 64) * A_STRIDE + ks) * 4);
    const uint32_t dB0 = (uint32_t)(A_FLOATS * 4 + (b_k * B_STRIDE + ns) * 4);
    const uint32_t dB1 = (uint32_t)(A_FLOATS * 4 + ((b_k + 8) * B_STRIDE + ns) * 4);

#pragma unroll
    for (int i = 0; i < 4; i++)
#pragma unroll
        for (int j = 0; j < 4; j++)
#pragma unroll
            for (int q = 0; q < 4; q++) acc[i][j][q] = 0.f;

    // prologue: stages 0..2 <- chunks 0..2
#pragma unroll
    for (int s = 0; s < NSTAGE - 1; s++) {
        uint32_t base = smb + s * STG_BYTES;
        size_t bo = (size_t)s * BK * bstride;
        CP16(base + dA0, aptr0 + s * BK);
        CP16(base + dA1, aptr1 + s * BK);
        CP16(base + dB0, bptr0 + bo);
        CP16(base + dB1, bptr1 + bo);
        CP_COMMIT();
    }

    for (int ch = 0; ch < NCH; ++ch) {
        CP_WAIT2();
        __syncthreads();

        const int s = ch & (NSTAGE - 1);
        const float* As = sm + s * STG_FLOATS;                 // [m][k] str 20
        const float* Bsm = sm + s * STG_FLOATS + A_FLOATS;     // [k][n] str 136

#pragma unroll
        for (int kh = 0; kh < 2; ++kh) {
            const int k0 = kh * 8;
            uint32_t af[4][4], bf[4][2];
#pragma unroll
            for (int mi = 0; mi < 4; mi++) {
                int rm = wm * 64 + mi * 16;
                const float* r0 = As + (rm + g8) * A_STRIDE + k0 + t4;
                const float* r1 = As + (rm + g8 + 8) * A_STRIDE + k0 + t4;
                af[mi][0] = __float_as_uint(r0[0]);
                af[mi][1] = __float_as_uint(r1[0]);
                af[mi][2] = __float_as_uint(r0[4]);
                af[mi][3] = __float_as_uint(r1[4]);
            }
#pragma unroll
            for (int ni = 0; ni < 4; ni++) {
                int cb = wn * 32 + ni * 8 + g8;
                bf[ni][0] = __float_as_uint(Bsm[(k0 + t4) * B_STRIDE + cb]);
                bf[ni][1] = __float_as_uint(Bsm[(k0 + t4 + 4) * B_STRIDE + cb]);
            }
#pragma unroll
            for (int mi = 0; mi < 4; mi++)
#pragma unroll
                for (int ni = 0; ni < 4; ni++)
                    mma_tf32(acc[mi][ni], af[mi], bf[ni]);
        }

        int nch = ch + NSTAGE - 1;
        if (nch < NCH) {
            uint32_t base = smb + (nch & (NSTAGE - 1)) * STG_BYTES;
            size_t bo = (size_t)nch * BK * bstride;
            CP16(base + dA0, aptr0 + nch * BK);
            CP16(base + dA1, aptr1 + nch * BK);
            CP16(base + dB0, bptr0 + bo);
            CP16(base + dB1, bptr1 + bo);
        }
        CP_COMMIT();   // commit every iter (possibly empty) to keep group count in sync
    }
}

// ---------------------------------------------------------------------------
// GEMM1: h[slot] = tf32round(gelu(Xr[tok] @ W1r[e] + b1[e]))
// ---------------------------------------------------------------------------
__global__ __launch_bounds__(256) void gemm1_mma(const float* __restrict__ b1)
{
    int e = blockIdx.z;
    int ne = g_cnt[e];
    int row0 = blockIdx.x * BM;
    if (row0 >= ne) return;
    int n0 = blockIdx.y * BN;

    extern __shared__ float sm[];
    uint32_t smb = smem_u32(sm);
    __shared__ int s_tok[BM];

    int tid = threadIdx.x;
    if (tid < BM) {
        int r = row0 + tid;
        s_tok[tid] = (r < ne) ? g_tok[e * T_ + r] : 0;
    }
    __syncthreads();

    const int a_row = tid >> 2, ks = (tid & 3) * 4;
    const int b_k = tid >> 5, ns = (tid & 31) * 4;
    const float* aptr0 = g_Xr + (size_t)s_tok[a_row] * D_ + ks;
    const float* aptr1 = g_Xr + (size_t)s_tok[a_row + 64] * D_ + ks;
    const float* bptr0 = g_W1r + (size_t)e * D_ * H_ + (size_t)b_k * H_ + n0 + ns;
    const float* bptr1 = bptr0 + (size_t)8 * H_;

    float acc[4][4][4];
    gemm_pipe<D_ / BK>(sm, smb, aptr0, aptr1, bptr0, bptr1, H_, acc);

    const int lane = tid & 31, wid = tid >> 5;
    const int wm = wid & 1, wn = wid >> 1;
    const int t4 = lane & 3, g8 = lane >> 2;
    const float* bb = b1 + (size_t)e * H_ + n0;
#pragma unroll
    for (int mi = 0; mi < 4; mi++) {
        int rl0 = wm * 64 + mi * 16 + g8;
#pragma unroll
        for (int half = 0; half < 2; half++) {
            int r = row0 + rl0 + half * 8;
            if (r >= ne) continue;
            float* orow = g_h + ((size_t)(e * T_ + r)) * H_ + n0;
#pragma unroll
            for (int ni = 0; ni < 4; ni++) {
                int cn = wn * 32 + ni * 8 + t4 * 2;
                float v0 = acc[mi][ni][half * 2]     + bb[cn];
                float v1 = acc[mi][ni][half * 2 + 1] + bb[cn + 1];
                float2 o;
                o.x = __uint_as_float(f2tf32(gelu_tanh(v0)));
                o.y = __uint_as_float(f2tf32(gelu_tanh(v1)));
                *(float2*)(orow + cn) = o;
            }
        }
    }
}

// ---------------------------------------------------------------------------
// GEMM2: out[tok] += w * (h[slot] @ W2r[e] + b2[e])
// ---------------------------------------------------------------------------
__global__ __launch_bounds__(256) void gemm2_mma(const float* __restrict__ b2,
                                                 float* __restrict__ out)
{
    int e = blockIdx.z;
    int ne = g_cnt[e];
    int row0 = blockIdx.x * BM;
    if (row0 >= ne) return;
    int n0 = blockIdx.y * BN;

    extern __shared__ float sm[];
    uint32_t smb = smem_u32(sm);

    int tid = threadIdx.x;
    const int a_row = tid >> 2, ks = (tid & 3) * 4;
    const int b_k = tid >> 5, ns = (tid & 31) * 4;
    // rows >= ne read stale-but-finite scratch; masked in epilogue
    const float* aptr0 = g_h + ((size_t)(e * T_ + row0 + a_row)) * H_ + ks;
    const float* aptr1 = g_h + ((size_t)(e * T_ + row0 + a_row + 64)) * H_ + ks;
    const float* bptr0 = g_W2r + (size_t)e * H_ * D_ + (size_t)b_k * D_ + n0 + ns;
    const float* bptr1 = bptr0 + (size_t)8 * D_;

    float acc[4][4][4];
    gemm_pipe<H_ / BK>(sm, smb, aptr0, aptr1, bptr0, bptr1, D_, acc);

    const int lane = tid & 31, wid = tid >> 5;
    const int wm = wid & 1, wn = wid >> 1;
    const int t4 = lane & 3, g8 = lane >> 2;
    const float* bb = b2 + (size_t)e * D_ + n0;
#pragma unroll
    for (int mi = 0; mi < 4; mi++) {
        int rl0 = wm * 64 + mi * 16 + g8;
#pragma unroll
        for (int half = 0; half < 2; half++) {
            int r = row0 + rl0 + half * 8;
            if (r >= ne) continue;
            int tok = g_tok[e * T_ + r];
            float wgt = g_wt[e * T_ + r];
            float* orow = out + (size_t)tok * D_ + n0;
#pragma unroll
            for (int ni = 0; ni < 4; ni++) {
                int cn = wn * 32 + ni * 8 + t4 * 2;
                atomicAdd(orow + cn,     wgt * (acc[mi][ni][half * 2]     + bb[cn]));
                atomicAdd(orow + cn + 1, wgt * (acc[mi][ni][half * 2 + 1] + bb[cn + 1]));
            }
        }
    }
}

// ---------------------------------------------------------------------------
extern "C" void kernel_launch(void* const* d_in, const int* in_sizes, int n_in,
                              void* d_out, int out_size)
{
    const float* x  = (const float*)d_in[0];
    const float* Wg = (const float*)d_in[1];
    const float* bg = (const float*)d_in[2];
    const float* W1 = (const float*)d_in[3];
    const float* b1 = (const float*)d_in[4];
    const float* W2 = (const float*)d_in[5];
    const float* b2 = (const float*)d_in[6];
    float* out = (float*)d_out;

    static int attr_set = 0;
    if (!attr_set) {
        cudaFuncSetAttribute(gemm1_mma, cudaFuncAttributeMaxDynamicSharedMemorySize, SMEM_BYTES);
        cudaFuncSetAttribute(gemm2_mma, cudaFuncAttributeMaxDynamicSharedMemorySize, SMEM_BYTES);
        attr_set = 1;
    }

    float* xr;  cudaGetSymbolAddress((void**)&xr,  g_Xr);
    float* w1r; cudaGetSymbolAddress((void**)&w1r, g_W1r);
    float* w2r; cudaGetSymbolAddress((void**)&w2r, g_W2r);

    zero_kernel<<<(T_ * D_) / (256 * 4), 256>>>(out);
    gate_kernel<<<T_, 256>>>(x, Wg, bg, out);
    rnd_kernel<<<(T_ * D_) / 1024, 256>>>(x, xr);
    rnd_kernel<<<(E_ * D_ * H_) / 1024, 256>>>(W1, w1r);
    rnd_kernel<<<(E_ * H_ * D_) / 1024, 256>>>(W2, w2r);
    gemm1_mma<<<dim3(T_ / BM, H_ / BN, E_), 256, SMEM_BYTES>>>(b1);
    gemm2_mma<<<dim3(T_ / BM, D_ / BN, E_), 256, SMEM_BYTES>>>(b2, out);
}